// round 12
// baseline (speedup 1.0000x reference)
#include <cuda_runtime.h>
#include <cuda_fp16.h>
#include <cstdint>
#include <math.h>

#define NN 50000
#define EE 100000
#define HH 512
#define TT 6
#define NTILE 3128                     /* 391 m-blocks x 8 jb */
#define EGRP 397                       /* ceil((EE + TT*256)/256) */
#define SORT_CAP (EE + TT * 256)

#define RSTR 24                        /* u32 stride per 32-k fp16 row in smem */
#define B_GU32 (64 * 16)               /* global B blob chunk: 64 rows x 16 u32 */

#define A_U32H   (128 * RSTR)                           /* 3072 */
#define B_U32H   (64 * RSTR)                            /* 1536 */
#define GRU_BOFFH (2 * A_U32H)                          /* 6144 */
#define GRU_STAGE_U32 (GRU_BOFFH + 6 * B_U32H)          /* 15360 */
#define GRU_HDR_U32  640
#define GRU_SMEMH ((GRU_HDR_U32 + 3 * GRU_STAGE_U32) * 4)   /* 186880 B */

#define EDGE_A_U32 (256 * RSTR)                         /* 6144 */
#define EDGE_STAGE_U32 (EDGE_A_U32 + B_U32H)            /* 7680 */
#define EDGE_HDR_U32 640
#define EDGE_SMEMH ((EDGE_HDR_U32 + 3 * EDGE_STAGE_U32) * 4) /* 94720 B */

/* ---------------- static device scratch ----------------------------------- */
__device__ unsigned g_emb16[(size_t)NN * 256];    /* fp16 interleaved, 256 u32/row */
__device__ unsigned g_prop16[(size_t)NN * 256];   /* fp16 interleaved accumulator  */
__device__ unsigned g_wswg[(size_t)6 * 8 * 16 * B_GU32];
__device__ unsigned g_wswe[(size_t)48 * 16 * B_GU32];
__device__ int g_sorted[SORT_CAP];
__device__ int g_tcount[TT];
__device__ int g_tcur[TT];
__device__ int g_toff[TT + 1];
__device__ int g_hdone;
__device__ int g_gtick;

/* ---------------- helpers -------------------------------------------------- */
__device__ __forceinline__ unsigned pk2h(float lo, float hi) {
    unsigned u;
    asm("cvt.rn.f16x2.f32 %0, %1, %2;" : "=r"(u) : "f"(hi), "f"(lo));
    return u;
}
__device__ __forceinline__ float sigmoidf_(float x) { return 1.0f / (1.0f + expf(-x)); }

__device__ __forceinline__ void mma16(float c[4], const unsigned a[4], uint2 b) {
    asm volatile(
        "mma.sync.aligned.m16n8k16.row.col.f32.f16.f16.f32 "
        "{%0,%1,%2,%3},{%4,%5,%6,%7},{%8,%9},{%0,%1,%2,%3};"
        : "+f"(c[0]), "+f"(c[1]), "+f"(c[2]), "+f"(c[3])
        : "r"(a[0]), "r"(a[1]), "r"(a[2]), "r"(a[3]), "r"(b.x), "r"(b.y));
}

__device__ __forceinline__ void redh2(unsigned* p, unsigned v) {
    asm volatile("red.global.add.noftz.f16x2 [%0], %1;"
                 :: "l"(p), "r"(v) : "memory");
}

#define CPA16(d, s) asm volatile("cp.async.ca.shared.global [%0], [%1], 16;" :: "r"(d), "l"(s))
#define CPA_COMMIT() asm volatile("cp.async.commit_group;" ::: "memory")
#define CPA_WAIT0()  asm volatile("cp.async.wait_group 0;" ::: "memory")
#define CPA_WAIT1()  asm volatile("cp.async.wait_group 1;" ::: "memory")

__device__ __forceinline__ uint32_t smem_u32(const void* p) {
    uint32_t a;
    asm("{ .reg .u64 t; cvta.to.shared.u64 t, %1; cvt.u32.u64 %0, t; }" : "=r"(a) : "l"(p));
    return a;
}

/* ---------------- init + meta (merged) ------------------------------------- */
__global__ void k_init(void) {
    size_t i = (size_t)blockIdx.x * blockDim.x + threadIdx.x;
    size_t n4 = (size_t)NN * 64;                   /* uint4 count of g_prop16 */
    if (i < n4) ((uint4*)g_prop16)[i] = make_uint4(0u, 0u, 0u, 0u);
    if (i < SORT_CAP) g_sorted[i] = -1;
    if (i < TT) { g_tcount[i] = 0; g_tcur[i] = 0; }
    if (i == 0) { g_hdone = 0; g_gtick = 0; }
}

/* hist with folded offsets (last block computes prefix) */
__global__ void k_hist(const int* __restrict__ et) {
    int e = blockIdx.x * blockDim.x + threadIdx.x;
    if (e < EE) atomicAdd(&g_tcount[et[e]], 1);
    __syncthreads();
    if (threadIdx.x == 0) {
        __threadfence();
        int old = atomicAdd(&g_hdone, 1);
        if (old == gridDim.x - 1) {
            int off = 0;
            for (int t = 0; t < TT; t++) {
                g_toff[t] = off;
                off += ((g_tcount[t] + 255) >> 8) << 8;   /* pad to 256 */
            }
            g_toff[TT] = off;
            __threadfence();
        }
    }
}

__global__ void k_scatter(const int* __restrict__ et) {
    int e = blockIdx.x * blockDim.x + threadIdx.x;
    if (e < EE) {
        int t = et[e];
        int pos = g_toff[t] + atomicAdd(&g_tcur[t], 1);
        g_sorted[pos] = e;
    }
}

/* ---------------- fused prep: edge W + GRU W + emb cvt ---------------------
 * blocks [0,768): edge W; [768,1536): GRU W; [1536,7786): emb fp16 convert. */
#define CVT_BLKS ((NN * 32 + 255) / 256)
__global__ void k_prep_all(
    const float* __restrict__ We,
    const float* __restrict__ W0, const float* __restrict__ W1,
    const float* __restrict__ W2, const float* __restrict__ W3,
    const float* __restrict__ W4, const float* __restrict__ W5,
    const float* __restrict__ emb, unsigned* __restrict__ e16)
{
    int b = blockIdx.x;
    int tid = threadIdx.x;
    if (b < 768) {                         /* edge weights */
        int kc = b & 15, jb = b >> 4;      /* jb 0..47 */
        int n = tid & 63, kg = tid >> 6;
        unsigned* dst = &g_wswe[(size_t)(jb * 16 + kc) * B_GU32];
#pragma unroll
        for (int p = 0; p < 4; p++) {
            int jp = kg * 4 + p;
            int kk = kc * 32 + jp * 2;
            float v0 = We[(size_t)kk * (TT * HH) + jb * 64 + n];
            float v1 = We[(size_t)(kk + 1) * (TT * HH) + jb * 64 + n];
            int g = jp >> 3, jj = jp & 7;
            dst[n * 16 + g * 8 + 2 * (jj & 3) + (jj >> 2)] = pk2h(v0, v1);
        }
    } else if (b < 1536) {                 /* GRU weights */
        int b2 = b - 768;
        int kc = b2 & 15, jb = (b2 >> 4) & 7, mat = b2 >> 7;
        const float* Ws[6] = {W0, W1, W2, W3, W4, W5};
        const float* W = Ws[mat];
        int n = tid & 63, kg = tid >> 6;
        unsigned* dst = &g_wswg[(size_t)((mat * 8 + jb) * 16 + kc) * B_GU32];
#pragma unroll
        for (int p = 0; p < 4; p++) {
            int jp = kg * 4 + p;
            int kk = kc * 32 + jp * 2;
            float v0 = W[(size_t)kk * HH + jb * 64 + n];
            float v1 = W[(size_t)(kk + 1) * HH + jb * 64 + n];
            int g = jp >> 3, jj = jp & 7;
            dst[n * 16 + g * 8 + 2 * (jj & 3) + (jj >> 2)] = pk2h(v0, v1);
        }
    } else {                               /* emb convert */
        size_t i = (size_t)(b - 1536) * 256 + tid;
        if (i >= (size_t)NN * 32) return;
        const float4* s4 = (const float4*)(emb + i * 16);
        float4 f0 = s4[0], f1 = s4[1], f2 = s4[2], f3 = s4[3];
        unsigned o[8];
        o[0] = pk2h(f0.x, f0.y); o[2] = pk2h(f0.z, f0.w);
        o[4] = pk2h(f1.x, f1.y); o[6] = pk2h(f1.z, f1.w);
        o[1] = pk2h(f2.x, f2.y); o[3] = pk2h(f2.z, f2.w);
        o[5] = pk2h(f3.x, f3.y); o[7] = pk2h(f3.z, f3.w);
        uint4* d4 = (uint4*)(e16 + i * 8);
        d4[0] = make_uint4(o[0], o[1], o[2], o[3]);
        d4[1] = make_uint4(o[4], o[5], o[6], o[7]);
    }
}

/* ---------------- fused GRU mma kernel (persistent, cross-tile pipelined) --
 * 512 threads, 16 warps, warp tile 32x16, tile 128x64. Continuous 3-slot
 * cp.async ring across tiles: next tile's chunks 0/1 fill during the tail
 * of the current tile; epilogue overlaps those fills.                       */
__device__ __forceinline__ void gru_fill(uint32_t st, int m0, int jb, int kc, int tid)
{
#pragma unroll
    for (int i = 0; i < 2; i++) {             /* A: 1024 CPA16 */
        int idx = i * 512 + tid;
        int mat = idx >> 9, rq = idx & 511, r = rq >> 2, q = rq & 3;
        int rg = m0 + r; if (rg > NN - 1) rg = NN - 1;
        const unsigned* s = (mat ? g_emb16 : g_prop16) + (size_t)rg * 256 + kc * 16 + q * 4;
        CPA16(st + (mat * A_U32H + r * RSTR + q * 4) * 4, (const void*)s);
    }
#pragma unroll
    for (int i = 0; i < 3; i++) {             /* B: 1536 CPA16 */
        int gidx = i * 512 + tid;
        int m_ = gidx >> 8, idx = gidx & 255, row = idx >> 2, c = idx & 3;
        const char* src = (const char*)&g_wswg[(size_t)((m_ * 8 + jb) * 16 + kc) * B_GU32];
        CPA16(st + (GRU_BOFFH + m_ * B_U32H + row * RSTR + c * 4) * 4, src + idx * 16);
    }
    CPA_COMMIT();
}

__global__ __launch_bounds__(512, 1) void k_gru_mma(
    const float* __restrict__ emb,
    const float* __restrict__ bir, const float* __restrict__ biz,
    const float* __restrict__ bin, const float* __restrict__ bhn,
    float* __restrict__ out)
{
    extern __shared__ unsigned smu[];
    float* bias_s = (float*)smu;                 /* [2][256] floats */
    int*   s_tick = (int*)(smu + 512);           /* [2] */
    unsigned* stage0 = smu + GRU_HDR_U32;
    uint32_t st0 = smem_u32(stage0);

    int tid = threadIdx.x, lane = tid & 31, warp = tid >> 5;
    int gid = lane >> 2, tig = lane & 3;
    int wm = (warp >> 2) * 32, wn = (warp & 3) * 16;

    if (tid == 0) s_tick[0] = atomicAdd(&g_gtick, 1);
    __syncthreads();
    int t = s_tick[0];
    if (t >= NTILE) return;
    int jb = t & 7, m0 = (t >> 3) * 128;
    int parity = 0, sb = 0;

    if (tid < 256) {
        const float* ba[4] = {bir, biz, bin, bhn};
        bias_s[tid] = ba[tid >> 6][jb * 64 + (tid & 63)];
    }
    gru_fill(st0 + (sb % 3) * GRU_STAGE_U32 * 4, m0, jb, 0, tid);
    gru_fill(st0 + ((sb + 1) % 3) * GRU_STAGE_U32 * 4, m0, jb, 1, tid);

    for (;;) {
        float accR[2][2][4], accZ[2][2][4], accN[2][2][4], accH[2][2][4];
#pragma unroll
        for (int mf = 0; mf < 2; mf++)
#pragma unroll
            for (int ni = 0; ni < 2; ni++)
#pragma unroll
                for (int q = 0; q < 4; q++) {
                    accR[mf][ni][q] = 0.f; accZ[mf][ni][q] = 0.f;
                    accN[mf][ni][q] = 0.f; accH[mf][ni][q] = 0.f;
                }

        int tn = -2, jbn = 0, m0n = 0;
        for (int c = 0; c < 16; c++) {
            if (c == 15 && tn < 0) CPA_WAIT0(); else CPA_WAIT1();
            __syncthreads();
            if (c == 12 && tid == 0) s_tick[parity ^ 1] = atomicAdd(&g_gtick, 1);
            if (c == 13) {
                tn = s_tick[parity ^ 1];
                if (tn >= NTILE) tn = -1;
                jbn = tn & 7; m0n = (tn >> 3) * 128;
            }
            if (c < 14) {
                gru_fill(st0 + ((sb + c + 2) % 3) * GRU_STAGE_U32 * 4, m0, jb, c + 2, tid);
            } else if (tn >= 0) {
                if (c == 14) {
                    gru_fill(st0 + ((sb + 16) % 3) * GRU_STAGE_U32 * 4, m0n, jbn, 0, tid);
                    if (tid < 256) {
                        const float* ba[4] = {bir, biz, bin, bhn};
                        bias_s[(parity ^ 1) * 256 + tid] = ba[tid >> 6][jbn * 64 + (tid & 63)];
                    }
                } else {
                    gru_fill(st0 + ((sb + 17) % 3) * GRU_STAGE_U32 * 4, m0n, jbn, 1, tid);
                }
            }

            const unsigned* cur = stage0 + ((sb + c) % 3) * GRU_STAGE_U32;
            const unsigned* Ap = cur;
            const unsigned* Ah = cur + A_U32H;
            const unsigned* Bb = cur + GRU_BOFFH;
#pragma unroll
            for (int ks = 0; ks < 2; ks++) {
                int ko = ks * 8 + tig * 2;
                unsigned ap[2][4], ah[2][4];
#pragma unroll
                for (int mf = 0; mf < 2; mf++) {
                    int r0 = wm + mf * 16 + gid;
                    uint2 v0 = *(const uint2*)(Ap + r0 * RSTR + ko);
                    uint2 v1 = *(const uint2*)(Ap + (r0 + 8) * RSTR + ko);
                    ap[mf][0] = v0.x; ap[mf][1] = v1.x; ap[mf][2] = v0.y; ap[mf][3] = v1.y;
                    uint2 w0 = *(const uint2*)(Ah + r0 * RSTR + ko);
                    uint2 w1 = *(const uint2*)(Ah + (r0 + 8) * RSTR + ko);
                    ah[mf][0] = w0.x; ah[mf][1] = w1.x; ah[mf][2] = w0.y; ah[mf][3] = w1.y;
                }
#pragma unroll
                for (int ni = 0; ni < 2; ni++) {
                    int cb = (wn + ni * 8 + gid) * RSTR + ko;
                    uint2 b;
                    b = *(const uint2*)(Bb + 0 * B_U32H + cb);   /* Wir */
#pragma unroll
                    for (int mf = 0; mf < 2; mf++) mma16(accR[mf][ni], ap[mf], b);
                    b = *(const uint2*)(Bb + 1 * B_U32H + cb);   /* Whr */
#pragma unroll
                    for (int mf = 0; mf < 2; mf++) mma16(accR[mf][ni], ah[mf], b);
                    b = *(const uint2*)(Bb + 2 * B_U32H + cb);   /* Wiz */
#pragma unroll
                    for (int mf = 0; mf < 2; mf++) mma16(accZ[mf][ni], ap[mf], b);
                    b = *(const uint2*)(Bb + 3 * B_U32H + cb);   /* Whz */
#pragma unroll
                    for (int mf = 0; mf < 2; mf++) mma16(accZ[mf][ni], ah[mf], b);
                    b = *(const uint2*)(Bb + 4 * B_U32H + cb);   /* Win */
#pragma unroll
                    for (int mf = 0; mf < 2; mf++) mma16(accN[mf][ni], ap[mf], b);
                    b = *(const uint2*)(Bb + 5 * B_U32H + cb);   /* Whn */
#pragma unroll
                    for (int mf = 0; mf < 2; mf++) mma16(accH[mf][ni], ah[mf], b);
                }
            }
        }

        /* epilogue: gates — overlaps next tile's in-flight fills */
        const float* bb = bias_s + parity * 256;
#pragma unroll
        for (int mf = 0; mf < 2; mf++) {
#pragma unroll
            for (int rp = 0; rp < 2; rp++) {
                int row = m0 + wm + mf * 16 + rp * 8 + gid;
                if (row >= NN) continue;
                const float* hrow = emb + (size_t)row * HH + jb * 64;
                float* orow = out + (size_t)row * HH + jb * 64;
#pragma unroll
                for (int ni = 0; ni < 2; ni++) {
                    int c0 = wn + ni * 8 + tig * 2;
                    float2 h2 = *(const float2*)(hrow + c0);
                    float o[2];
#pragma unroll
                    for (int e = 0; e < 2; e++) {
                        int q = rp * 2 + e;
                        int cl = c0 + e;
                        float r = sigmoidf_(accR[mf][ni][q] + bb[cl]);
                        float z = sigmoidf_(accZ[mf][ni][q] + bb[64 + cl]);
                        float n = tanhf(accN[mf][ni][q] + bb[128 + cl]
                                        + r * (accH[mf][ni][q] + bb[192 + cl]));
                        float h = e ? h2.y : h2.x;
                        o[e] = (1.f - z) * n + z * h;
                    }
                    *(float2*)(orow + c0) = make_float2(o[0], o[1]);
                }
            }
        }
        if (tn < 0) return;
        t = tn; jb = jbn; m0 = m0n;
        parity ^= 1; sb = (sb + 1) % 3;
    }
}

/* ---------------- edge mma kernel ------------------------------------------
 * 256 threads, 8 warps, warp tile 64x32, CTA tile 256x64. 3-stage pipe,
 * 2 CTAs/SM. fp16x2 REDs directly into interleaved g_prop16.                */
__device__ __forceinline__ void edge_fill(uint32_t st, const int* __restrict__ ssrc,
                                          int jbg, int kc, int tid)
{
#pragma unroll
    for (int i = 0; i < 4; i++) {             /* A: 1024 CPA16 */
        int idx = i * 256 + tid, r = idx >> 2, q = idx & 3;
        int nr = ssrc[r]; if (nr < 0) nr = 0;
        const unsigned* s = g_emb16 + (size_t)nr * 256 + kc * 16 + q * 4;
        CPA16(st + (r * RSTR + q * 4) * 4, (const void*)s);
    }
    {                                          /* B: 256 CPA16 */
        int row = tid >> 2, c = tid & 3;
        const char* src = (const char*)&g_wswe[(size_t)(jbg * 16 + kc) * B_GU32];
        CPA16(st + (EDGE_A_U32 + row * RSTR + c * 4) * 4, src + tid * 16);
    }
    CPA_COMMIT();
}

__global__ __launch_bounds__(256, 2) void k_edge_mma(
    const int* __restrict__ src, const int* __restrict__ dst,
    const float* __restrict__ b_edge)
{
    int start = blockIdx.y * 256;
    if (start >= g_toff[TT]) return;
    int t = 0;
#pragma unroll
    for (int i = 1; i < TT; i++) if (start >= g_toff[i]) t = i;
    int jb8 = blockIdx.x;
    int jbg = t * 8 + jb8;

    extern __shared__ unsigned smu[];
    int* s_srow = (int*)smu;             /* 256 */
    int* s_dst  = (int*)smu + 256;       /* 256 */
    float* s_bias = (float*)smu + 512;   /* 64  */
    unsigned* stage0 = smu + EDGE_HDR_U32;
    uint32_t st0 = smem_u32(stage0);

    int tid = threadIdx.x, lane = tid & 31, warp = tid >> 5;
    int gid = lane >> 2, tig = lane & 3;
    int wm = (warp >> 1) * 64, wn = (warp & 1) * 32;

    {
        int e = g_sorted[start + tid];
        s_srow[tid] = (e >= 0) ? src[e] : -1;
        s_dst[tid]  = (e >= 0) ? dst[e] : -1;
    }
    if (tid < 64) s_bias[tid] = b_edge[(size_t)t * HH + jb8 * 64 + tid];
    __syncthreads();

    float acc[4][4][4];
#pragma unroll
    for (int mf = 0; mf < 4; mf++)
#pragma unroll
        for (int ni = 0; ni < 4; ni++)
#pragma unroll
            for (int q = 0; q < 4; q++) acc[mf][ni][q] = 0.f;

    edge_fill(st0, s_srow, jbg, 0, tid);
    edge_fill(st0 + EDGE_STAGE_U32 * 4, s_srow, jbg, 1, tid);

    for (int c = 0; c < 16; c++) {
        if (c < 15) CPA_WAIT1(); else CPA_WAIT0();
        __syncthreads();
        if (c + 2 < 16)
            edge_fill(st0 + ((c + 2) % 3) * EDGE_STAGE_U32 * 4, s_srow, jbg, c + 2, tid);

        const unsigned* cur = stage0 + (c % 3) * EDGE_STAGE_U32;
        const unsigned* Ap = cur;
        const unsigned* Bb = cur + EDGE_A_U32;
#pragma unroll
        for (int ks = 0; ks < 2; ks++) {
            int ko = ks * 8 + tig * 2;
            unsigned ap[4][4];
#pragma unroll
            for (int mf = 0; mf < 4; mf++) {
                int r0 = wm + mf * 16 + gid;
                uint2 v0 = *(const uint2*)(Ap + r0 * RSTR + ko);
                uint2 v1 = *(const uint2*)(Ap + (r0 + 8) * RSTR + ko);
                ap[mf][0] = v0.x; ap[mf][1] = v1.x; ap[mf][2] = v0.y; ap[mf][3] = v1.y;
            }
#pragma unroll
            for (int ni = 0; ni < 4; ni++) {
                uint2 b = *(const uint2*)(Bb + (wn + ni * 8 + gid) * RSTR + ko);
#pragma unroll
                for (int mf = 0; mf < 4; mf++) mma16(acc[mf][ni], ap[mf], b);
            }
        }
    }

    /* epilogue: bias + fp16x2 scatter reduction into interleaved g_prop16 */
#pragma unroll
    for (int mf = 0; mf < 4; mf++) {
#pragma unroll
        for (int rp = 0; rp < 2; rp++) {
            int arow = wm + mf * 16 + rp * 8 + gid;
            int d = s_dst[arow];
            if (d < 0) continue;
            unsigned* prow = g_prop16 + (size_t)d * 256;
#pragma unroll
            for (int ni = 0; ni < 4; ni++) {
                int cl = wn + ni * 8 + tig * 2;          /* local col (even) */
                int c0 = jb8 * 64 + cl;                  /* global col       */
                int pg = (c0 >> 1) & 7;                  /* pair in 16-group */
                int u32idx = (c0 >> 4) * 8 + 2 * (pg & 3) + (pg >> 2);
                unsigned v = pk2h(acc[mf][ni][rp * 2]     + s_bias[cl],
                                  acc[mf][ni][rp * 2 + 1] + s_bias[cl + 1]);
                redh2(prow + u32idx, v);
            }
        }
    }
}

/* ---------------- launch --------------------------------------------------- */
extern "C" void kernel_launch(void* const* d_in, const int* in_sizes, int n_in,
                              void* d_out, int out_size)
{
    int s = (n_in >= 18) ? 2 : 0;

    const float* emb    = (const float*)d_in[0];
    const int*   src    = (const int*)d_in[1];
    const int*   dst    = (const int*)d_in[2];
    const int*   et     = (const int*)d_in[3];
    const float* W_edge = (const float*)d_in[4 + s];
    const float* b_edge = (const float*)d_in[5 + s];
    const float* Wir    = (const float*)d_in[6 + s];
    const float* Wiz    = (const float*)d_in[7 + s];
    const float* Win    = (const float*)d_in[8 + s];
    const float* bir    = (const float*)d_in[9 + s];
    const float* biz    = (const float*)d_in[10 + s];
    const float* bin    = (const float*)d_in[11 + s];
    const float* Whr    = (const float*)d_in[12 + s];
    const float* Whz    = (const float*)d_in[13 + s];
    const float* Whn    = (const float*)d_in[14 + s];
    const float* bhn    = (const float*)d_in[15 + s];
    float* out = (float*)d_out;

    unsigned* d_e16;  cudaGetSymbolAddress((void**)&d_e16, g_emb16);

    static int attr_done = 0;
    if (!attr_done) {
        cudaFuncSetAttribute(k_gru_mma,  cudaFuncAttributeMaxDynamicSharedMemorySize, GRU_SMEMH);
        cudaFuncSetAttribute(k_edge_mma, cudaFuncAttributeMaxDynamicSharedMemorySize, EDGE_SMEMH);
        attr_done = 1;
    }

    k_init<<<(NN * 64 + 255) / 256, 256>>>();
    k_hist<<<(EE + 255) / 256, 256>>>(et);
    k_scatter<<<(EE + 255) / 256, 256>>>(et);

    k_prep_all<<<1536 + CVT_BLKS, 256>>>(W_edge, Wir, Whr, Wiz, Whz, Win, Whn,
                                         emb, d_e16);

    k_edge_mma<<<dim3(8, EGRP), 256, EDGE_SMEMH>>>(src, dst, b_edge);

    k_gru_mma<<<148, 512, GRU_SMEMH>>>(emb, bir, biz, bin, bhn, out);
}

// round 13
// speedup vs baseline: 1.0392x; 1.0392x over previous
#include <cuda_runtime.h>
#include <cuda_fp16.h>
#include <cstdint>
#include <math.h>

#define NN 50000
#define EE 100000
#define HH 512
#define TT 6
#define NTILE 3128                     /* 391 m-blocks x 8 jb */
#define EGRP 397                       /* ceil((EE + TT*256)/256) */
#define SORT_CAP (EE + TT * 256)

#define RSTR 24                        /* u32 stride per 32-k fp16 row in smem */
#define B_GU32 (64 * 16)               /* global B blob chunk: 64 rows x 16 u32 */

#define A_U32H   (128 * RSTR)                           /* 3072 */
#define B_U32H   (64 * RSTR)                            /* 1536 */
#define GRU_BOFFH (2 * A_U32H)                          /* 6144 */
#define GRU_STAGE_U32 (GRU_BOFFH + 6 * B_U32H)          /* 15360 */
#define GRU_HDR_U32  320
#define GRU_SMEMH ((GRU_HDR_U32 + 3 * GRU_STAGE_U32) * 4)   /* 185600 B */

#define EDGE_A_U32 (256 * RSTR)                         /* 6144 */
#define EDGE_STAGE_U32 (EDGE_A_U32 + B_U32H)            /* 7680 */
#define EDGE_HDR_U32 640
#define EDGE_SMEMH ((EDGE_HDR_U32 + 3 * EDGE_STAGE_U32) * 4) /* 94720 B */

/* ---------------- static device scratch ----------------------------------- */
__device__ unsigned g_emb16[(size_t)NN * 256];    /* fp16 interleaved, 256 u32/row */
__device__ unsigned g_prop16[(size_t)NN * 256];   /* fp16 interleaved accumulator  */
__device__ unsigned g_wswg[(size_t)6 * 8 * 16 * B_GU32];
__device__ unsigned g_wswe[(size_t)48 * 16 * B_GU32];
__device__ int g_sorted[SORT_CAP];
__device__ int g_tcount[TT];
__device__ int g_tcur[TT];
__device__ int g_toff[TT + 1];
__device__ int g_hdone;
__device__ int g_gtick;

/* ---------------- helpers -------------------------------------------------- */
__device__ __forceinline__ unsigned pk2h(float lo, float hi) {
    unsigned u;
    asm("cvt.rn.f16x2.f32 %0, %1, %2;" : "=r"(u) : "f"(hi), "f"(lo));
    return u;
}
__device__ __forceinline__ float sigmoidf_(float x) { return 1.0f / (1.0f + expf(-x)); }

__device__ __forceinline__ void mma16(float c[4], const unsigned a[4], uint2 b) {
    asm volatile(
        "mma.sync.aligned.m16n8k16.row.col.f32.f16.f16.f32 "
        "{%0,%1,%2,%3},{%4,%5,%6,%7},{%8,%9},{%0,%1,%2,%3};"
        : "+f"(c[0]), "+f"(c[1]), "+f"(c[2]), "+f"(c[3])
        : "r"(a[0]), "r"(a[1]), "r"(a[2]), "r"(a[3]), "r"(b.x), "r"(b.y));
}

__device__ __forceinline__ void redh2(unsigned* p, unsigned v) {
    asm volatile("red.global.add.noftz.f16x2 [%0], %1;"
                 :: "l"(p), "r"(v) : "memory");
}

#define CPA16(d, s) asm volatile("cp.async.ca.shared.global [%0], [%1], 16;" :: "r"(d), "l"(s))
#define CPA_COMMIT() asm volatile("cp.async.commit_group;" ::: "memory")
#define CPA_WAIT0()  asm volatile("cp.async.wait_group 0;" ::: "memory")
#define CPA_WAIT1()  asm volatile("cp.async.wait_group 1;" ::: "memory")

__device__ __forceinline__ uint32_t smem_u32(const void* p) {
    uint32_t a;
    asm("{ .reg .u64 t; cvta.to.shared.u64 t, %1; cvt.u32.u64 %0, t; }" : "=r"(a) : "l"(p));
    return a;
}

/* ---------------- small meta init ------------------------------------------ */
__global__ void k_init(void) {
    int i = blockIdx.x * blockDim.x + threadIdx.x;
    if (i < SORT_CAP) g_sorted[i] = -1;
    if (i < TT) { g_tcount[i] = 0; g_tcur[i] = 0; }
    if (i == 0) { g_hdone = 0; g_gtick = 0; }
}

/* hist with folded offsets (last block computes prefix) */
__global__ void k_hist(const int* __restrict__ et) {
    int e = blockIdx.x * blockDim.x + threadIdx.x;
    if (e < EE) atomicAdd(&g_tcount[et[e]], 1);
    __syncthreads();
    if (threadIdx.x == 0) {
        __threadfence();
        int old = atomicAdd(&g_hdone, 1);
        if (old == gridDim.x - 1) {
            int off = 0;
            for (int t = 0; t < TT; t++) {
                g_toff[t] = off;
                off += ((g_tcount[t] + 255) >> 8) << 8;   /* pad to 256 */
            }
            g_toff[TT] = off;
            __threadfence();
        }
    }
}

__global__ void k_scatter(const int* __restrict__ et) {
    int e = blockIdx.x * blockDim.x + threadIdx.x;
    if (e < EE) {
        int t = et[e];
        int pos = g_toff[t] + atomicAdd(&g_tcur[t], 1);
        g_sorted[pos] = e;
    }
}

/* ---------------- fused prep: edge W + GRU W + emb cvt + prop16 zero --------
 * blocks [0,768): edge W; [768,1536): GRU W; [1536,1536+CVT): emb convert;
 * [1536+CVT, +ZB): zero g_prop16.                                            */
#define CVT_BLKS ((NN * 32 + 255) / 256)
#define ZERO_BLKS ((NN * 64 + 255) / 256)
__global__ void k_prep_all(
    const float* __restrict__ We,
    const float* __restrict__ W0, const float* __restrict__ W1,
    const float* __restrict__ W2, const float* __restrict__ W3,
    const float* __restrict__ W4, const float* __restrict__ W5,
    const float* __restrict__ emb, unsigned* __restrict__ e16)
{
    int b = blockIdx.x;
    int tid = threadIdx.x;
    if (b < 768) {                         /* edge weights */
        int kc = b & 15, jb = b >> 4;      /* jb 0..47 */
        int n = tid & 63, kg = tid >> 6;
        unsigned* dst = &g_wswe[(size_t)(jb * 16 + kc) * B_GU32];
#pragma unroll
        for (int p = 0; p < 4; p++) {
            int jp = kg * 4 + p;
            int kk = kc * 32 + jp * 2;
            float v0 = We[(size_t)kk * (TT * HH) + jb * 64 + n];
            float v1 = We[(size_t)(kk + 1) * (TT * HH) + jb * 64 + n];
            int g = jp >> 3, jj = jp & 7;
            dst[n * 16 + g * 8 + 2 * (jj & 3) + (jj >> 2)] = pk2h(v0, v1);
        }
    } else if (b < 1536) {                 /* GRU weights */
        int b2 = b - 768;
        int kc = b2 & 15, jb = (b2 >> 4) & 7, mat = b2 >> 7;
        const float* Ws[6] = {W0, W1, W2, W3, W4, W5};
        const float* W = Ws[mat];
        int n = tid & 63, kg = tid >> 6;
        unsigned* dst = &g_wswg[(size_t)((mat * 8 + jb) * 16 + kc) * B_GU32];
#pragma unroll
        for (int p = 0; p < 4; p++) {
            int jp = kg * 4 + p;
            int kk = kc * 32 + jp * 2;
            float v0 = W[(size_t)kk * HH + jb * 64 + n];
            float v1 = W[(size_t)(kk + 1) * HH + jb * 64 + n];
            int g = jp >> 3, jj = jp & 7;
            dst[n * 16 + g * 8 + 2 * (jj & 3) + (jj >> 2)] = pk2h(v0, v1);
        }
    } else if (b < 1536 + CVT_BLKS) {      /* emb convert */
        size_t i = (size_t)(b - 1536) * 256 + tid;
        if (i >= (size_t)NN * 32) return;
        const float4* s4 = (const float4*)(emb + i * 16);
        float4 f0 = s4[0], f1 = s4[1], f2 = s4[2], f3 = s4[3];
        unsigned o[8];
        o[0] = pk2h(f0.x, f0.y); o[2] = pk2h(f0.z, f0.w);
        o[4] = pk2h(f1.x, f1.y); o[6] = pk2h(f1.z, f1.w);
        o[1] = pk2h(f2.x, f2.y); o[3] = pk2h(f2.z, f2.w);
        o[5] = pk2h(f3.x, f3.y); o[7] = pk2h(f3.z, f3.w);
        uint4* d4 = (uint4*)(e16 + i * 8);
        d4[0] = make_uint4(o[0], o[1], o[2], o[3]);
        d4[1] = make_uint4(o[4], o[5], o[6], o[7]);
    } else {                               /* zero g_prop16 */
        size_t i = (size_t)(b - 1536 - CVT_BLKS) * 256 + tid;
        if (i < (size_t)NN * 64)
            ((uint4*)g_prop16)[i] = make_uint4(0u, 0u, 0u, 0u);
    }
}

/* ---------------- fused GRU mma kernel (persistent, R11 form) ---------------
 * 512 threads, 16 warps, warp tile 32x16, tile 128x64, 3-stage pipe.
 * 160 resident CTAs pull tile tickets (jb fastest) from g_gtick.            */
__device__ __forceinline__ void gru_fill(uint32_t st, int m0, int jb, int kc, int tid)
{
#pragma unroll
    for (int i = 0; i < 2; i++) {             /* A: 1024 CPA16 */
        int idx = i * 512 + tid;
        int mat = idx >> 9, rq = idx & 511, r = rq >> 2, q = rq & 3;
        int rg = m0 + r; if (rg > NN - 1) rg = NN - 1;
        const unsigned* s = (mat ? g_emb16 : g_prop16) + (size_t)rg * 256 + kc * 16 + q * 4;
        CPA16(st + (mat * A_U32H + r * RSTR + q * 4) * 4, (const void*)s);
    }
#pragma unroll
    for (int i = 0; i < 3; i++) {             /* B: 1536 CPA16 */
        int gidx = i * 512 + tid;
        int m_ = gidx >> 8, idx = gidx & 255, row = idx >> 2, c = idx & 3;
        const char* src = (const char*)&g_wswg[(size_t)((m_ * 8 + jb) * 16 + kc) * B_GU32];
        CPA16(st + (GRU_BOFFH + m_ * B_U32H + row * RSTR + c * 4) * 4, src + idx * 16);
    }
    CPA_COMMIT();
}

__global__ __launch_bounds__(512, 1) void k_gru_mma(
    const float* __restrict__ emb,
    const float* __restrict__ bir, const float* __restrict__ biz,
    const float* __restrict__ bin, const float* __restrict__ bhn,
    float* __restrict__ out)
{
    extern __shared__ unsigned smu[];
    float* bias_s = (float*)smu;                 /* 256 floats */
    int*   s_tick = (int*)(smu + 256);
    unsigned* stage0 = smu + GRU_HDR_U32;
    uint32_t st0 = smem_u32(stage0);

    int tid = threadIdx.x, lane = tid & 31, warp = tid >> 5;
    int gid = lane >> 2, tig = lane & 3;
    int wm = (warp >> 2) * 32, wn = (warp & 3) * 16;

    for (;;) {
        if (tid == 0) *s_tick = atomicAdd(&g_gtick, 1);
        __syncthreads();
        int t = *s_tick;
        if (t >= NTILE) return;
        int jb = t & 7, m0 = (t >> 3) * 128;

        if (tid < 256) {
            const float* ba[4] = {bir, biz, bin, bhn};
            bias_s[tid] = ba[tid >> 6][jb * 64 + (tid & 63)];
        }

        float accR[2][2][4], accZ[2][2][4], accN[2][2][4], accH[2][2][4];
#pragma unroll
        for (int mf = 0; mf < 2; mf++)
#pragma unroll
            for (int ni = 0; ni < 2; ni++)
#pragma unroll
                for (int q = 0; q < 4; q++) {
                    accR[mf][ni][q] = 0.f; accZ[mf][ni][q] = 0.f;
                    accN[mf][ni][q] = 0.f; accH[mf][ni][q] = 0.f;
                }

        gru_fill(st0, m0, jb, 0, tid);
        gru_fill(st0 + GRU_STAGE_U32 * 4, m0, jb, 1, tid);

        for (int c = 0; c < 16; c++) {
            if (c < 15) CPA_WAIT1(); else CPA_WAIT0();
            __syncthreads();
            if (c + 2 < 16)
                gru_fill(st0 + ((c + 2) % 3) * GRU_STAGE_U32 * 4, m0, jb, c + 2, tid);

            const unsigned* cur = stage0 + (c % 3) * GRU_STAGE_U32;
            const unsigned* Ap = cur;
            const unsigned* Ah = cur + A_U32H;
            const unsigned* Bb = cur + GRU_BOFFH;
#pragma unroll
            for (int ks = 0; ks < 2; ks++) {
                int ko = ks * 8 + tig * 2;
                unsigned ap[2][4], ah[2][4];
#pragma unroll
                for (int mf = 0; mf < 2; mf++) {
                    int r0 = wm + mf * 16 + gid;
                    uint2 v0 = *(const uint2*)(Ap + r0 * RSTR + ko);
                    uint2 v1 = *(const uint2*)(Ap + (r0 + 8) * RSTR + ko);
                    ap[mf][0] = v0.x; ap[mf][1] = v1.x; ap[mf][2] = v0.y; ap[mf][3] = v1.y;
                    uint2 w0 = *(const uint2*)(Ah + r0 * RSTR + ko);
                    uint2 w1 = *(const uint2*)(Ah + (r0 + 8) * RSTR + ko);
                    ah[mf][0] = w0.x; ah[mf][1] = w1.x; ah[mf][2] = w0.y; ah[mf][3] = w1.y;
                }
#pragma unroll
                for (int ni = 0; ni < 2; ni++) {
                    int cb = (wn + ni * 8 + gid) * RSTR + ko;
                    uint2 b;
                    b = *(const uint2*)(Bb + 0 * B_U32H + cb);   /* Wir */
#pragma unroll
                    for (int mf = 0; mf < 2; mf++) mma16(accR[mf][ni], ap[mf], b);
                    b = *(const uint2*)(Bb + 1 * B_U32H + cb);   /* Whr */
#pragma unroll
                    for (int mf = 0; mf < 2; mf++) mma16(accR[mf][ni], ah[mf], b);
                    b = *(const uint2*)(Bb + 2 * B_U32H + cb);   /* Wiz */
#pragma unroll
                    for (int mf = 0; mf < 2; mf++) mma16(accZ[mf][ni], ap[mf], b);
                    b = *(const uint2*)(Bb + 3 * B_U32H + cb);   /* Whz */
#pragma unroll
                    for (int mf = 0; mf < 2; mf++) mma16(accZ[mf][ni], ah[mf], b);
                    b = *(const uint2*)(Bb + 4 * B_U32H + cb);   /* Win */
#pragma unroll
                    for (int mf = 0; mf < 2; mf++) mma16(accN[mf][ni], ap[mf], b);
                    b = *(const uint2*)(Bb + 5 * B_U32H + cb);   /* Whn */
#pragma unroll
                    for (int mf = 0; mf < 2; mf++) mma16(accH[mf][ni], ah[mf], b);
                }
            }
        }

        /* epilogue: gates (h read in fp32) */
#pragma unroll
        for (int mf = 0; mf < 2; mf++) {
#pragma unroll
            for (int rp = 0; rp < 2; rp++) {
                int row = m0 + wm + mf * 16 + rp * 8 + gid;
                if (row >= NN) continue;
                const float* hrow = emb + (size_t)row * HH + jb * 64;
                float* orow = out + (size_t)row * HH + jb * 64;
#pragma unroll
                for (int ni = 0; ni < 2; ni++) {
                    int c0 = wn + ni * 8 + tig * 2;
                    float2 h2 = *(const float2*)(hrow + c0);
                    float o[2];
#pragma unroll
                    for (int e = 0; e < 2; e++) {
                        int q = rp * 2 + e;
                        int cl = c0 + e;
                        float r = sigmoidf_(accR[mf][ni][q] + bias_s[cl]);
                        float z = sigmoidf_(accZ[mf][ni][q] + bias_s[64 + cl]);
                        float n = tanhf(accN[mf][ni][q] + bias_s[128 + cl]
                                        + r * (accH[mf][ni][q] + bias_s[192 + cl]));
                        float h = e ? h2.y : h2.x;
                        o[e] = (1.f - z) * n + z * h;
                    }
                    *(float2*)(orow + c0) = make_float2(o[0], o[1]);
                }
            }
        }
        __syncthreads();     /* protect bias_s / stages before next tile */
    }
}

/* ---------------- edge mma kernel ------------------------------------------
 * 256 threads, 8 warps, warp tile 64x32, CTA tile 256x64. 3-stage pipe,
 * 2 CTAs/SM. fp16x2 REDs directly into interleaved g_prop16.                */
__device__ __forceinline__ void edge_fill(uint32_t st, const int* __restrict__ ssrc,
                                          int jbg, int kc, int tid)
{
#pragma unroll
    for (int i = 0; i < 4; i++) {             /* A: 1024 CPA16 */
        int idx = i * 256 + tid, r = idx >> 2, q = idx & 3;
        int nr = ssrc[r]; if (nr < 0) nr = 0;
        const unsigned* s = g_emb16 + (size_t)nr * 256 + kc * 16 + q * 4;
        CPA16(st + (r * RSTR + q * 4) * 4, (const void*)s);
    }
    {                                          /* B: 256 CPA16 */
        int row = tid >> 2, c = tid & 3;
        const char* src = (const char*)&g_wswe[(size_t)(jbg * 16 + kc) * B_GU32];
        CPA16(st + (EDGE_A_U32 + row * RSTR + c * 4) * 4, src + tid * 16);
    }
    CPA_COMMIT();
}

__global__ __launch_bounds__(256, 2) void k_edge_mma(
    const int* __restrict__ src, const int* __restrict__ dst,
    const float* __restrict__ b_edge)
{
    int start = blockIdx.y * 256;
    if (start >= g_toff[TT]) return;
    int t = 0;
#pragma unroll
    for (int i = 1; i < TT; i++) if (start >= g_toff[i]) t = i;
    int jb8 = blockIdx.x;
    int jbg = t * 8 + jb8;

    extern __shared__ unsigned smu[];
    int* s_srow = (int*)smu;             /* 256 */
    int* s_dst  = (int*)smu + 256;       /* 256 */
    float* s_bias = (float*)smu + 512;   /* 64  */
    unsigned* stage0 = smu + EDGE_HDR_U32;
    uint32_t st0 = smem_u32(stage0);

    int tid = threadIdx.x, lane = tid & 31, warp = tid >> 5;
    int gid = lane >> 2, tig = lane & 3;
    int wm = (warp >> 1) * 64, wn = (warp & 1) * 32;

    {
        int e = g_sorted[start + tid];
        s_srow[tid] = (e >= 0) ? src[e] : -1;
        s_dst[tid]  = (e >= 0) ? dst[e] : -1;
    }
    if (tid < 64) s_bias[tid] = b_edge[(size_t)t * HH + jb8 * 64 + tid];
    __syncthreads();

    float acc[4][4][4];
#pragma unroll
    for (int mf = 0; mf < 4; mf++)
#pragma unroll
        for (int ni = 0; ni < 4; ni++)
#pragma unroll
            for (int q = 0; q < 4; q++) acc[mf][ni][q] = 0.f;

    edge_fill(st0, s_srow, jbg, 0, tid);
    edge_fill(st0 + EDGE_STAGE_U32 * 4, s_srow, jbg, 1, tid);

    for (int c = 0; c < 16; c++) {
        if (c < 15) CPA_WAIT1(); else CPA_WAIT0();
        __syncthreads();
        if (c + 2 < 16)
            edge_fill(st0 + ((c + 2) % 3) * EDGE_STAGE_U32 * 4, s_srow, jbg, c + 2, tid);

        const unsigned* cur = stage0 + (c % 3) * EDGE_STAGE_U32;
        const unsigned* Ap = cur;
        const unsigned* Bb = cur + EDGE_A_U32;
#pragma unroll
        for (int ks = 0; ks < 2; ks++) {
            int ko = ks * 8 + tig * 2;
            unsigned ap[4][4];
#pragma unroll
            for (int mf = 0; mf < 4; mf++) {
                int r0 = wm + mf * 16 + gid;
                uint2 v0 = *(const uint2*)(Ap + r0 * RSTR + ko);
                uint2 v1 = *(const uint2*)(Ap + (r0 + 8) * RSTR + ko);
                ap[mf][0] = v0.x; ap[mf][1] = v1.x; ap[mf][2] = v0.y; ap[mf][3] = v1.y;
            }
#pragma unroll
            for (int ni = 0; ni < 4; ni++) {
                uint2 b = *(const uint2*)(Bb + (wn + ni * 8 + gid) * RSTR + ko);
#pragma unroll
                for (int mf = 0; mf < 4; mf++) mma16(acc[mf][ni], ap[mf], b);
            }
        }
    }

    /* epilogue: bias + fp16x2 scatter reduction into interleaved g_prop16 */
#pragma unroll
    for (int mf = 0; mf < 4; mf++) {
#pragma unroll
        for (int rp = 0; rp < 2; rp++) {
            int arow = wm + mf * 16 + rp * 8 + gid;
            int d = s_dst[arow];
            if (d < 0) continue;
            unsigned* prow = g_prop16 + (size_t)d * 256;
#pragma unroll
            for (int ni = 0; ni < 4; ni++) {
                int cl = wn + ni * 8 + tig * 2;          /* local col (even) */
                int c0 = jb8 * 64 + cl;                  /* global col       */
                int pg = (c0 >> 1) & 7;                  /* pair in 16-group */
                int u32idx = (c0 >> 4) * 8 + 2 * (pg & 3) + (pg >> 2);
                unsigned v = pk2h(acc[mf][ni][rp * 2]     + s_bias[cl],
                                  acc[mf][ni][rp * 2 + 1] + s_bias[cl + 1]);
                redh2(prow + u32idx, v);
            }
        }
    }
}

/* ---------------- launch --------------------------------------------------- */
extern "C" void kernel_launch(void* const* d_in, const int* in_sizes, int n_in,
                              void* d_out, int out_size)
{
    int s = (n_in >= 18) ? 2 : 0;

    const float* emb    = (const float*)d_in[0];
    const int*   src    = (const int*)d_in[1];
    const int*   dst    = (const int*)d_in[2];
    const int*   et     = (const int*)d_in[3];
    const float* W_edge = (const float*)d_in[4 + s];
    const float* b_edge = (const float*)d_in[5 + s];
    const float* Wir    = (const float*)d_in[6 + s];
    const float* Wiz    = (const float*)d_in[7 + s];
    const float* Win    = (const float*)d_in[8 + s];
    const float* bir    = (const float*)d_in[9 + s];
    const float* biz    = (const float*)d_in[10 + s];
    const float* bin    = (const float*)d_in[11 + s];
    const float* Whr    = (const float*)d_in[12 + s];
    const float* Whz    = (const float*)d_in[13 + s];
    const float* Whn    = (const float*)d_in[14 + s];
    const float* bhn    = (const float*)d_in[15 + s];
    float* out = (float*)d_out;

    unsigned* d_e16;  cudaGetSymbolAddress((void**)&d_e16, g_emb16);

    static int attr_done = 0;
    if (!attr_done) {
        cudaFuncSetAttribute(k_gru_mma,  cudaFuncAttributeMaxDynamicSharedMemorySize, GRU_SMEMH);
        cudaFuncSetAttribute(k_edge_mma, cudaFuncAttributeMaxDynamicSharedMemorySize, EDGE_SMEMH);
        attr_done = 1;
    }

    k_init<<<(SORT_CAP + 255) / 256, 256>>>();
    k_hist<<<(EE + 255) / 256, 256>>>(et);
    k_scatter<<<(EE + 255) / 256, 256>>>(et);

    k_prep_all<<<1536 + CVT_BLKS + ZERO_BLKS, 256>>>(
        W_edge, Wir, Whr, Wiz, Whz, Win, Whn, emb, d_e16);

    k_edge_mma<<<dim3(8, EGRP), 256, EDGE_SMEMH>>>(src, dst, b_edge);

    k_gru_mma<<<160, 512, GRU_SMEMH>>>(emb, bir, biz, bin, bhn, out);
}

// round 14
// speedup vs baseline: 1.0410x; 1.0017x over previous
#include <cuda_runtime.h>
#include <cuda_fp16.h>
#include <cstdint>
#include <math.h>

#define NN 50000
#define EE 100000
#define HH 512
#define TT 6
#define NTILE 3128                     /* 391 m-blocks x 8 jb */
#define EGRP 397                       /* ceil((EE + TT*256)/256) */
#define SORT_CAP (EE + TT * 256)

#define RSTR 24                        /* u32 stride per 32-k fp16 row in smem */
#define B_GU32 (64 * 16)               /* global B blob chunk: 64 rows x 16 u32 */

#define A_U32H   (128 * RSTR)                           /* 3072 */
#define B_U32H   (64 * RSTR)                            /* 1536 */
#define GRU_BOFFH (2 * A_U32H)                          /* 6144 */
#define GRU_STAGE_U32 (GRU_BOFFH + 6 * B_U32H)          /* 15360 */
#define GRU_HDR_U32  320
#define GRU_SMEMH ((GRU_HDR_U32 + 3 * GRU_STAGE_U32) * 4)   /* 185600 B */

#define EDGE_A_U32 (256 * RSTR)                         /* 6144 */
#define EDGE_STAGE_U32 (EDGE_A_U32 + B_U32H)            /* 7680 */
#define EDGE_HDR_U32 640
#define EDGE_SMEMH ((EDGE_HDR_U32 + 3 * EDGE_STAGE_U32) * 4) /* 94720 B */

/* ---------------- static device scratch ----------------------------------- */
__device__ unsigned g_emb16[(size_t)NN * 256];    /* fp16 interleaved, 256 u32/row */
__device__ unsigned g_prop16[(size_t)NN * 256];   /* fp16 interleaved accumulator  */
__device__ unsigned g_wswg[(size_t)6 * 8 * 16 * B_GU32];
__device__ unsigned g_wswe[(size_t)48 * 16 * B_GU32];
__device__ int g_sorted[SORT_CAP];
__device__ int g_tcount[TT];
__device__ int g_tcur[TT];
__device__ int g_toff[TT + 1];
__device__ int g_hdone;
__device__ int g_gtick;

/* ---------------- helpers -------------------------------------------------- */
__device__ __forceinline__ unsigned pk2h(float lo, float hi) {
    unsigned u;
    asm("cvt.rn.f16x2.f32 %0, %1, %2;" : "=r"(u) : "f"(hi), "f"(lo));
    return u;
}
__device__ __forceinline__ float sigmoidf_(float x) { return 1.0f / (1.0f + expf(-x)); }

__device__ __forceinline__ void mma16(float c[4], const unsigned a[4], uint2 b) {
    asm volatile(
        "mma.sync.aligned.m16n8k16.row.col.f32.f16.f16.f32 "
        "{%0,%1,%2,%3},{%4,%5,%6,%7},{%8,%9},{%0,%1,%2,%3};"
        : "+f"(c[0]), "+f"(c[1]), "+f"(c[2]), "+f"(c[3])
        : "r"(a[0]), "r"(a[1]), "r"(a[2]), "r"(a[3]), "r"(b.x), "r"(b.y));
}

__device__ __forceinline__ void redh2(unsigned* p, unsigned v) {
    asm volatile("red.global.add.noftz.f16x2 [%0], %1;"
                 :: "l"(p), "r"(v) : "memory");
}

#define CPA16(d, s) asm volatile("cp.async.ca.shared.global [%0], [%1], 16;" :: "r"(d), "l"(s))
#define CPA_COMMIT() asm volatile("cp.async.commit_group;" ::: "memory")
#define CPA_WAIT0()  asm volatile("cp.async.wait_group 0;" ::: "memory")
#define CPA_WAIT1()  asm volatile("cp.async.wait_group 1;" ::: "memory")

__device__ __forceinline__ uint32_t smem_u32(const void* p) {
    uint32_t a;
    asm("{ .reg .u64 t; cvta.to.shared.u64 t, %1; cvt.u32.u64 %0, t; }" : "=r"(a) : "l"(p));
    return a;
}

/* ---------------- small meta init ------------------------------------------ */
__global__ void k_init(void) {
    int i = blockIdx.x * blockDim.x + threadIdx.x;
    if (i < SORT_CAP) g_sorted[i] = -1;
    if (i < TT) { g_tcount[i] = 0; g_tcur[i] = 0; }
    if (i == 0) { g_hdone = 0; g_gtick = 0; }
}

/* hist with folded offsets (last block computes prefix) */
__global__ void k_hist(const int* __restrict__ et) {
    int e = blockIdx.x * blockDim.x + threadIdx.x;
    if (e < EE) atomicAdd(&g_tcount[et[e]], 1);
    __syncthreads();
    if (threadIdx.x == 0) {
        __threadfence();
        int old = atomicAdd(&g_hdone, 1);
        if (old == gridDim.x - 1) {
            int off = 0;
            for (int t = 0; t < TT; t++) {
                g_toff[t] = off;
                off += ((g_tcount[t] + 255) >> 8) << 8;   /* pad to 256 */
            }
            g_toff[TT] = off;
            __threadfence();
        }
    }
}

__global__ void k_scatter(const int* __restrict__ et) {
    int e = blockIdx.x * blockDim.x + threadIdx.x;
    if (e < EE) {
        int t = et[e];
        int pos = g_toff[t] + atomicAdd(&g_tcur[t], 1);
        g_sorted[pos] = e;
    }
}

/* ---------------- fused prep: edge W + GRU W + emb cvt + prop16 zero --------
 * blocks [0,768): edge W; [768,1536): GRU W; [1536,1536+CVT): emb convert;
 * [1536+CVT, +ZB): zero g_prop16.                                            */
#define CVT_BLKS ((NN * 32 + 255) / 256)
#define ZERO_BLKS ((NN * 64 + 255) / 256)
__global__ void k_prep_all(
    const float* __restrict__ We,
    const float* __restrict__ W0, const float* __restrict__ W1,
    const float* __restrict__ W2, const float* __restrict__ W3,
    const float* __restrict__ W4, const float* __restrict__ W5,
    const float* __restrict__ emb, unsigned* __restrict__ e16)
{
    int b = blockIdx.x;
    int tid = threadIdx.x;
    if (b < 768) {                         /* edge weights */
        int kc = b & 15, jb = b >> 4;      /* jb 0..47 */
        int n = tid & 63, kg = tid >> 6;
        unsigned* dst = &g_wswe[(size_t)(jb * 16 + kc) * B_GU32];
#pragma unroll
        for (int p = 0; p < 4; p++) {
            int jp = kg * 4 + p;
            int kk = kc * 32 + jp * 2;
            float v0 = We[(size_t)kk * (TT * HH) + jb * 64 + n];
            float v1 = We[(size_t)(kk + 1) * (TT * HH) + jb * 64 + n];
            int g = jp >> 3, jj = jp & 7;
            dst[n * 16 + g * 8 + 2 * (jj & 3) + (jj >> 2)] = pk2h(v0, v1);
        }
    } else if (b < 1536) {                 /* GRU weights */
        int b2 = b - 768;
        int kc = b2 & 15, jb = (b2 >> 4) & 7, mat = b2 >> 7;
        const float* Ws[6] = {W0, W1, W2, W3, W4, W5};
        const float* W = Ws[mat];
        int n = tid & 63, kg = tid >> 6;
        unsigned* dst = &g_wswg[(size_t)((mat * 8 + jb) * 16 + kc) * B_GU32];
#pragma unroll
        for (int p = 0; p < 4; p++) {
            int jp = kg * 4 + p;
            int kk = kc * 32 + jp * 2;
            float v0 = W[(size_t)kk * HH + jb * 64 + n];
            float v1 = W[(size_t)(kk + 1) * HH + jb * 64 + n];
            int g = jp >> 3, jj = jp & 7;
            dst[n * 16 + g * 8 + 2 * (jj & 3) + (jj >> 2)] = pk2h(v0, v1);
        }
    } else if (b < 1536 + CVT_BLKS) {      /* emb convert */
        size_t i = (size_t)(b - 1536) * 256 + tid;
        if (i >= (size_t)NN * 32) return;
        const float4* s4 = (const float4*)(emb + i * 16);
        float4 f0 = s4[0], f1 = s4[1], f2 = s4[2], f3 = s4[3];
        unsigned o[8];
        o[0] = pk2h(f0.x, f0.y); o[2] = pk2h(f0.z, f0.w);
        o[4] = pk2h(f1.x, f1.y); o[6] = pk2h(f1.z, f1.w);
        o[1] = pk2h(f2.x, f2.y); o[3] = pk2h(f2.z, f2.w);
        o[5] = pk2h(f3.x, f3.y); o[7] = pk2h(f3.z, f3.w);
        uint4* d4 = (uint4*)(e16 + i * 8);
        d4[0] = make_uint4(o[0], o[1], o[2], o[3]);
        d4[1] = make_uint4(o[4], o[5], o[6], o[7]);
    } else {                               /* zero g_prop16 */
        size_t i = (size_t)(b - 1536 - CVT_BLKS) * 256 + tid;
        if (i < (size_t)NN * 64)
            ((uint4*)g_prop16)[i] = make_uint4(0u, 0u, 0u, 0u);
    }
}

/* ---------------- fused GRU mma kernel (persistent) -------------------------
 * 512 threads, 16 warps, warp tile 32x16, tile 128x64, 3-stage pipe.
 * 160 resident CTAs pull tile tickets (jb fastest) from g_gtick.            */
__device__ __forceinline__ void gru_fill(uint32_t st, int m0, int jb, int kc, int tid)
{
#pragma unroll
    for (int i = 0; i < 2; i++) {             /* A: 1024 CPA16 */
        int idx = i * 512 + tid;
        int mat = idx >> 9, rq = idx & 511, r = rq >> 2, q = rq & 3;
        int rg = m0 + r; if (rg > NN - 1) rg = NN - 1;
        const unsigned* s = (mat ? g_emb16 : g_prop16) + (size_t)rg * 256 + kc * 16 + q * 4;
        CPA16(st + (mat * A_U32H + r * RSTR + q * 4) * 4, (const void*)s);
    }
#pragma unroll
    for (int i = 0; i < 3; i++) {             /* B: 1536 CPA16 */
        int gidx = i * 512 + tid;
        int m_ = gidx >> 8, idx = gidx & 255, row = idx >> 2, c = idx & 3;
        const char* src = (const char*)&g_wswg[(size_t)((m_ * 8 + jb) * 16 + kc) * B_GU32];
        CPA16(st + (GRU_BOFFH + m_ * B_U32H + row * RSTR + c * 4) * 4, src + idx * 16);
    }
    CPA_COMMIT();
}

__global__ __launch_bounds__(512, 1) void k_gru_mma(
    const float* __restrict__ emb,
    const float* __restrict__ bir, const float* __restrict__ biz,
    const float* __restrict__ bin, const float* __restrict__ bhn,
    float* __restrict__ out)
{
    extern __shared__ unsigned smu[];
    float* bias_s = (float*)smu;                 /* 256 floats */
    int*   s_tick = (int*)(smu + 256);
    unsigned* stage0 = smu + GRU_HDR_U32;
    uint32_t st0 = smem_u32(stage0);

    int tid = threadIdx.x, lane = tid & 31, warp = tid >> 5;
    int gid = lane >> 2, tig = lane & 3;
    int wm = (warp >> 2) * 32, wn = (warp & 3) * 16;

    for (;;) {
        if (tid == 0) *s_tick = atomicAdd(&g_gtick, 1);
        __syncthreads();
        int t = *s_tick;
        if (t >= NTILE) return;
        int jb = t & 7, m0 = (t >> 3) * 128;

        if (tid < 256) {
            const float* ba[4] = {bir, biz, bin, bhn};
            bias_s[tid] = ba[tid >> 6][jb * 64 + (tid & 63)];
        }

        float accR[2][2][4], accZ[2][2][4], accN[2][2][4], accH[2][2][4];
#pragma unroll
        for (int mf = 0; mf < 2; mf++)
#pragma unroll
            for (int ni = 0; ni < 2; ni++)
#pragma unroll
                for (int q = 0; q < 4; q++) {
                    accR[mf][ni][q] = 0.f; accZ[mf][ni][q] = 0.f;
                    accN[mf][ni][q] = 0.f; accH[mf][ni][q] = 0.f;
                }

        gru_fill(st0, m0, jb, 0, tid);
        gru_fill(st0 + GRU_STAGE_U32 * 4, m0, jb, 1, tid);

        for (int c = 0; c < 16; c++) {
            if (c < 15) CPA_WAIT1(); else CPA_WAIT0();
            __syncthreads();
            if (c + 2 < 16)
                gru_fill(st0 + ((c + 2) % 3) * GRU_STAGE_U32 * 4, m0, jb, c + 2, tid);

            const unsigned* cur = stage0 + (c % 3) * GRU_STAGE_U32;
            const unsigned* Ap = cur;
            const unsigned* Ah = cur + A_U32H;
            const unsigned* Bb = cur + GRU_BOFFH;
#pragma unroll
            for (int ks = 0; ks < 2; ks++) {
                int ko = ks * 8 + tig * 2;
                unsigned ap[2][4], ah[2][4];
#pragma unroll
                for (int mf = 0; mf < 2; mf++) {
                    int r0 = wm + mf * 16 + gid;
                    uint2 v0 = *(const uint2*)(Ap + r0 * RSTR + ko);
                    uint2 v1 = *(const uint2*)(Ap + (r0 + 8) * RSTR + ko);
                    ap[mf][0] = v0.x; ap[mf][1] = v1.x; ap[mf][2] = v0.y; ap[mf][3] = v1.y;
                    uint2 w0 = *(const uint2*)(Ah + r0 * RSTR + ko);
                    uint2 w1 = *(const uint2*)(Ah + (r0 + 8) * RSTR + ko);
                    ah[mf][0] = w0.x; ah[mf][1] = w1.x; ah[mf][2] = w0.y; ah[mf][3] = w1.y;
                }
#pragma unroll
                for (int ni = 0; ni < 2; ni++) {
                    int cb = (wn + ni * 8 + gid) * RSTR + ko;
                    uint2 b;
                    b = *(const uint2*)(Bb + 0 * B_U32H + cb);   /* Wir */
#pragma unroll
                    for (int mf = 0; mf < 2; mf++) mma16(accR[mf][ni], ap[mf], b);
                    b = *(const uint2*)(Bb + 1 * B_U32H + cb);   /* Whr */
#pragma unroll
                    for (int mf = 0; mf < 2; mf++) mma16(accR[mf][ni], ah[mf], b);
                    b = *(const uint2*)(Bb + 2 * B_U32H + cb);   /* Wiz */
#pragma unroll
                    for (int mf = 0; mf < 2; mf++) mma16(accZ[mf][ni], ap[mf], b);
                    b = *(const uint2*)(Bb + 3 * B_U32H + cb);   /* Whz */
#pragma unroll
                    for (int mf = 0; mf < 2; mf++) mma16(accZ[mf][ni], ah[mf], b);
                    b = *(const uint2*)(Bb + 4 * B_U32H + cb);   /* Win */
#pragma unroll
                    for (int mf = 0; mf < 2; mf++) mma16(accN[mf][ni], ap[mf], b);
                    b = *(const uint2*)(Bb + 5 * B_U32H + cb);   /* Whn */
#pragma unroll
                    for (int mf = 0; mf < 2; mf++) mma16(accH[mf][ni], ah[mf], b);
                }
            }
        }

        /* epilogue: gates (h read in fp32) */
#pragma unroll
        for (int mf = 0; mf < 2; mf++) {
#pragma unroll
            for (int rp = 0; rp < 2; rp++) {
                int row = m0 + wm + mf * 16 + rp * 8 + gid;
                if (row >= NN) continue;
                const float* hrow = emb + (size_t)row * HH + jb * 64;
                float* orow = out + (size_t)row * HH + jb * 64;
#pragma unroll
                for (int ni = 0; ni < 2; ni++) {
                    int c0 = wn + ni * 8 + tig * 2;
                    float2 h2 = *(const float2*)(hrow + c0);
                    float o[2];
#pragma unroll
                    for (int e = 0; e < 2; e++) {
                        int q = rp * 2 + e;
                        int cl = c0 + e;
                        float r = sigmoidf_(accR[mf][ni][q] + bias_s[cl]);
                        float z = sigmoidf_(accZ[mf][ni][q] + bias_s[64 + cl]);
                        float n = tanhf(accN[mf][ni][q] + bias_s[128 + cl]
                                        + r * (accH[mf][ni][q] + bias_s[192 + cl]));
                        float h = e ? h2.y : h2.x;
                        o[e] = (1.f - z) * n + z * h;
                    }
                    *(float2*)(orow + c0) = make_float2(o[0], o[1]);
                }
            }
        }
        __syncthreads();     /* protect bias_s / stages before next tile */
    }
}

/* ---------------- edge mma kernel ------------------------------------------
 * 256 threads, 8 warps, warp tile 64x32, CTA tile 256x64. 3-stage pipe,
 * 2 CTAs/SM. fp16x2 REDs directly into interleaved g_prop16.                */
__device__ __forceinline__ void edge_fill(uint32_t st, const int* __restrict__ ssrc,
                                          int jbg, int kc, int tid)
{
#pragma unroll
    for (int i = 0; i < 4; i++) {             /* A: 1024 CPA16 */
        int idx = i * 256 + tid, r = idx >> 2, q = idx & 3;
        int nr = ssrc[r]; if (nr < 0) nr = 0;
        const unsigned* s = g_emb16 + (size_t)nr * 256 + kc * 16 + q * 4;
        CPA16(st + (r * RSTR + q * 4) * 4, (const void*)s);
    }
    {                                          /* B: 256 CPA16 */
        int row = tid >> 2, c = tid & 3;
        const char* src = (const char*)&g_wswe[(size_t)(jbg * 16 + kc) * B_GU32];
        CPA16(st + (EDGE_A_U32 + row * RSTR + c * 4) * 4, src + tid * 16);
    }
    CPA_COMMIT();
}

__global__ __launch_bounds__(256, 2) void k_edge_mma(
    const int* __restrict__ src, const int* __restrict__ dst,
    const float* __restrict__ b_edge)
{
    int start = blockIdx.y * 256;
    if (start >= g_toff[TT]) return;
    int t = 0;
#pragma unroll
    for (int i = 1; i < TT; i++) if (start >= g_toff[i]) t = i;
    int jb8 = blockIdx.x;
    int jbg = t * 8 + jb8;

    extern __shared__ unsigned smu[];
    int* s_srow = (int*)smu;             /* 256 */
    int* s_dst  = (int*)smu + 256;       /* 256 */
    float* s_bias = (float*)smu + 512;   /* 64  */
    unsigned* stage0 = smu + EDGE_HDR_U32;
    uint32_t st0 = smem_u32(stage0);

    int tid = threadIdx.x, lane = tid & 31, warp = tid >> 5;
    int gid = lane >> 2, tig = lane & 3;
    int wm = (warp >> 1) * 64, wn = (warp & 1) * 32;

    {
        int e = g_sorted[start + tid];
        s_srow[tid] = (e >= 0) ? src[e] : -1;
        s_dst[tid]  = (e >= 0) ? dst[e] : -1;
    }
    if (tid < 64) s_bias[tid] = b_edge[(size_t)t * HH + jb8 * 64 + tid];
    __syncthreads();

    float acc[4][4][4];
#pragma unroll
    for (int mf = 0; mf < 4; mf++)
#pragma unroll
        for (int ni = 0; ni < 4; ni++)
#pragma unroll
            for (int q = 0; q < 4; q++) acc[mf][ni][q] = 0.f;

    edge_fill(st0, s_srow, jbg, 0, tid);
    edge_fill(st0 + EDGE_STAGE_U32 * 4, s_srow, jbg, 1, tid);

    for (int c = 0; c < 16; c++) {
        if (c < 15) CPA_WAIT1(); else CPA_WAIT0();
        __syncthreads();
        if (c + 2 < 16)
            edge_fill(st0 + ((c + 2) % 3) * EDGE_STAGE_U32 * 4, s_srow, jbg, c + 2, tid);

        const unsigned* cur = stage0 + (c % 3) * EDGE_STAGE_U32;
        const unsigned* Ap = cur;
        const unsigned* Bb = cur + EDGE_A_U32;
#pragma unroll
        for (int ks = 0; ks < 2; ks++) {
            int ko = ks * 8 + tig * 2;
            unsigned ap[4][4];
#pragma unroll
            for (int mf = 0; mf < 4; mf++) {
                int r0 = wm + mf * 16 + gid;
                uint2 v0 = *(const uint2*)(Ap + r0 * RSTR + ko);
                uint2 v1 = *(const uint2*)(Ap + (r0 + 8) * RSTR + ko);
                ap[mf][0] = v0.x; ap[mf][1] = v1.x; ap[mf][2] = v0.y; ap[mf][3] = v1.y;
            }
#pragma unroll
            for (int ni = 0; ni < 4; ni++) {
                uint2 b = *(const uint2*)(Bb + (wn + ni * 8 + gid) * RSTR + ko);
#pragma unroll
                for (int mf = 0; mf < 4; mf++) mma16(acc[mf][ni], ap[mf], b);
            }
        }
    }

    /* epilogue: bias + fp16x2 scatter reduction into interleaved g_prop16 */
#pragma unroll
    for (int mf = 0; mf < 4; mf++) {
#pragma unroll
        for (int rp = 0; rp < 2; rp++) {
            int arow = wm + mf * 16 + rp * 8 + gid;
            int d = s_dst[arow];
            if (d < 0) continue;
            unsigned* prow = g_prop16 + (size_t)d * 256;
#pragma unroll
            for (int ni = 0; ni < 4; ni++) {
                int cl = wn + ni * 8 + tig * 2;          /* local col (even) */
                int c0 = jb8 * 64 + cl;                  /* global col       */
                int pg = (c0 >> 1) & 7;                  /* pair in 16-group */
                int u32idx = (c0 >> 4) * 8 + 2 * (pg & 3) + (pg >> 2);
                unsigned v = pk2h(acc[mf][ni][rp * 2]     + s_bias[cl],
                                  acc[mf][ni][rp * 2 + 1] + s_bias[cl + 1]);
                redh2(prow + u32idx, v);
            }
        }
    }
}

/* ---------------- launch --------------------------------------------------- */
extern "C" void kernel_launch(void* const* d_in, const int* in_sizes, int n_in,
                              void* d_out, int out_size)
{
    int s = (n_in >= 18) ? 2 : 0;

    const float* emb    = (const float*)d_in[0];
    const int*   src    = (const int*)d_in[1];
    const int*   dst    = (const int*)d_in[2];
    const int*   et     = (const int*)d_in[3];
    const float* W_edge = (const float*)d_in[4 + s];
    const float* b_edge = (const float*)d_in[5 + s];
    const float* Wir    = (const float*)d_in[6 + s];
    const float* Wiz    = (const float*)d_in[7 + s];
    const float* Win    = (const float*)d_in[8 + s];
    const float* bir    = (const float*)d_in[9 + s];
    const float* biz    = (const float*)d_in[10 + s];
    const float* bin    = (const float*)d_in[11 + s];
    const float* Whr    = (const float*)d_in[12 + s];
    const float* Whz    = (const float*)d_in[13 + s];
    const float* Whn    = (const float*)d_in[14 + s];
    const float* bhn    = (const float*)d_in[15 + s];
    float* out = (float*)d_out;

    unsigned* d_e16;  cudaGetSymbolAddress((void**)&d_e16, g_emb16);

    static int init_done = 0;
    static cudaStream_t s2 = 0;
    static cudaEvent_t ev1 = 0, ev2 = 0;
    if (!init_done) {
        cudaFuncSetAttribute(k_gru_mma,  cudaFuncAttributeMaxDynamicSharedMemorySize, GRU_SMEMH);
        cudaFuncSetAttribute(k_edge_mma, cudaFuncAttributeMaxDynamicSharedMemorySize, EDGE_SMEMH);
        if (cudaStreamCreateWithFlags(&s2, cudaStreamNonBlocking) != cudaSuccess) s2 = 0;
        if (s2) {
            if (cudaEventCreateWithFlags(&ev1, cudaEventDisableTiming) != cudaSuccess) { ev1 = 0; }
            if (cudaEventCreateWithFlags(&ev2, cudaEventDisableTiming) != cudaSuccess) { ev2 = 0; }
            if (!ev1 || !ev2) s2 = 0;
        }
        init_done = 1;
    }

    if (s2) {
        /* fork: prep on s2 concurrent with sort chain on default stream */
        cudaEventRecord(ev1, 0);
        cudaStreamWaitEvent(s2, ev1, 0);
        k_prep_all<<<1536 + CVT_BLKS + ZERO_BLKS, 256, 0, s2>>>(
            W_edge, Wir, Whr, Wiz, Whz, Win, Whn, emb, d_e16);
        cudaEventRecord(ev2, s2);

        k_init<<<(SORT_CAP + 255) / 256, 256>>>();
        k_hist<<<(EE + 255) / 256, 256>>>(et);
        k_scatter<<<(EE + 255) / 256, 256>>>(et);

        cudaStreamWaitEvent((cudaStream_t)0, ev2, 0);
    } else {
        k_init<<<(SORT_CAP + 255) / 256, 256>>>();
        k_hist<<<(EE + 255) / 256, 256>>>(et);
        k_scatter<<<(EE + 255) / 256, 256>>>(et);
        k_prep_all<<<1536 + CVT_BLKS + ZERO_BLKS, 256>>>(
            W_edge, Wir, Whr, Wiz, Whz, Win, Whn, emb, d_e16);
    }

    k_edge_mma<<<dim3(8, EGRP), 256, EDGE_SMEMH>>>(src, dst, b_edge);

    k_gru_mma<<<160, 512, GRU_SMEMH>>>(emb, bir, biz, bin, bhn, out);
}

// round 15
// speedup vs baseline: 1.0709x; 1.0287x over previous
#include <cuda_runtime.h>
#include <cuda_fp16.h>
#include <cstdint>
#include <math.h>

#define NN 50000
#define EE 100000
#define HH 512
#define TT 6
#define NTILE 3128                     /* 391 m-blocks x 8 jb */
#define EGRP 397                       /* ceil((EE + TT*256)/256) */
#define SORT_CAP (EE + TT * 256)

#define RSTR 24                        /* u32 stride per 32-k fp16 row in smem */
#define B_GU32 (64 * 16)               /* global B blob chunk: 64 rows x 16 u32 */

#define A_U32H   (128 * RSTR)                           /* 3072 */
#define B_U32H   (64 * RSTR)                            /* 1536 */
#define GRU_BOFFH (2 * A_U32H)                          /* 6144 */
#define GRU_STAGE_U32 (GRU_BOFFH + 6 * B_U32H)          /* 15360 */
#define GRU_HDR_U32  320
#define GRU_SMEMH ((GRU_HDR_U32 + 3 * GRU_STAGE_U32) * 4)   /* 185600 B */

#define EDGE_A_U32 (256 * RSTR)                         /* 6144 */
#define EDGE_STAGE_U32 (EDGE_A_U32 + B_U32H)            /* 7680 */
#define EDGE_HDR_U32 640
#define EDGE_SMEMH ((EDGE_HDR_U32 + 3 * EDGE_STAGE_U32) * 4) /* 94720 B */

/* ---------------- static device scratch ----------------------------------- */
__device__ unsigned g_emb16[(size_t)NN * 256];    /* fp16 interleaved, 256 u32/row */
__device__ unsigned g_prop16[(size_t)NN * 256];   /* fp16 interleaved accumulator  */
__device__ unsigned g_wswg[(size_t)6 * 8 * 16 * B_GU32];
__device__ unsigned g_wswe[(size_t)48 * 16 * B_GU32];
__device__ int g_sorted[SORT_CAP];
__device__ int g_tcount[TT];
__device__ int g_tcur[TT];
__device__ int g_toff[TT + 1];
__device__ int g_hdone;
__device__ int g_gtick;

/* ---------------- helpers -------------------------------------------------- */
__device__ __forceinline__ unsigned pk2h(float lo, float hi) {
    unsigned u;
    asm("cvt.rn.f16x2.f32 %0, %1, %2;" : "=r"(u) : "f"(hi), "f"(lo));
    return u;
}
__device__ __forceinline__ float sigmoidf_(float x) { return 1.0f / (1.0f + expf(-x)); }

__device__ __forceinline__ void mma16(float c[4], const unsigned a[4], uint2 b) {
    asm volatile(
        "mma.sync.aligned.m16n8k16.row.col.f32.f16.f16.f32 "
        "{%0,%1,%2,%3},{%4,%5,%6,%7},{%8,%9},{%0,%1,%2,%3};"
        : "+f"(c[0]), "+f"(c[1]), "+f"(c[2]), "+f"(c[3])
        : "r"(a[0]), "r"(a[1]), "r"(a[2]), "r"(a[3]), "r"(b.x), "r"(b.y));
}

__device__ __forceinline__ void redh2(unsigned* p, unsigned v) {
    asm volatile("red.global.add.noftz.f16x2 [%0], %1;"
                 :: "l"(p), "r"(v) : "memory");
}

#define CPA16(d, s) asm volatile("cp.async.ca.shared.global [%0], [%1], 16;" :: "r"(d), "l"(s))
#define CPA_COMMIT() asm volatile("cp.async.commit_group;" ::: "memory")
#define CPA_WAIT0()  asm volatile("cp.async.wait_group 0;" ::: "memory")
#define CPA_WAIT1()  asm volatile("cp.async.wait_group 1;" ::: "memory")

__device__ __forceinline__ uint32_t smem_u32(const void* p) {
    uint32_t a;
    asm("{ .reg .u64 t; cvta.to.shared.u64 t, %1; cvt.u32.u64 %0, t; }" : "=r"(a) : "l"(p));
    return a;
}

/* ---------------- small meta init ------------------------------------------ */
__global__ void k_init(void) {
    int i = blockIdx.x * blockDim.x + threadIdx.x;
    if (i < SORT_CAP) g_sorted[i] = -1;
    if (i < TT) { g_tcount[i] = 0; g_tcur[i] = 0; }
    if (i == 0) { g_hdone = 0; g_gtick = 0; }
}

/* hist: warp-aggregated atomics + folded offsets (last block does prefix) */
__global__ void k_hist(const int* __restrict__ et) {
    int e = blockIdx.x * blockDim.x + threadIdx.x;
    int lane = threadIdx.x & 31;
    int t = (e < EE) ? et[e] : -1;
    unsigned mask = __match_any_sync(0xffffffffu, t);
    if (t >= 0) {
        int leader = __ffs(mask) - 1;
        if (lane == leader) atomicAdd(&g_tcount[t], __popc(mask));
    }
    __syncthreads();
    if (threadIdx.x == 0) {
        __threadfence();
        int old = atomicAdd(&g_hdone, 1);
        if (old == gridDim.x - 1) {
            int off = 0;
            for (int tt = 0; tt < TT; tt++) {
                g_toff[tt] = off;
                off += ((g_tcount[tt] + 255) >> 8) << 8;   /* pad to 256 */
            }
            g_toff[TT] = off;
            __threadfence();
        }
    }
}

/* scatter: warp-aggregated slot allocation */
__global__ void k_scatter(const int* __restrict__ et) {
    int e = blockIdx.x * blockDim.x + threadIdx.x;
    int lane = threadIdx.x & 31;
    int t = (e < EE) ? et[e] : -1;
    unsigned mask = __match_any_sync(0xffffffffu, t);
    if (t >= 0) {
        int leader = __ffs(mask) - 1;
        int base = 0;
        if (lane == leader) base = atomicAdd(&g_tcur[t], __popc(mask));
        base = __shfl_sync(mask, base, leader);
        int rank = __popc(mask & ((1u << lane) - 1u));
        g_sorted[g_toff[t] + base + rank] = e;
    }
}

/* ---------------- fused prep: edge W + GRU W + emb cvt + prop16 zero --------
 * blocks [0,768): edge W; [768,1536): GRU W; [1536,1536+CVT): emb convert;
 * [1536+CVT, +ZB): zero g_prop16.                                            */
#define CVT_BLKS ((NN * 32 + 255) / 256)
#define ZERO_BLKS ((NN * 64 + 255) / 256)
__global__ void k_prep_all(
    const float* __restrict__ We,
    const float* __restrict__ W0, const float* __restrict__ W1,
    const float* __restrict__ W2, const float* __restrict__ W3,
    const float* __restrict__ W4, const float* __restrict__ W5,
    const float* __restrict__ emb, unsigned* __restrict__ e16)
{
    int b = blockIdx.x;
    int tid = threadIdx.x;
    if (b < 768) {                         /* edge weights */
        int kc = b & 15, jb = b >> 4;      /* jb 0..47 */
        int n = tid & 63, kg = tid >> 6;
        unsigned* dst = &g_wswe[(size_t)(jb * 16 + kc) * B_GU32];
#pragma unroll
        for (int p = 0; p < 4; p++) {
            int jp = kg * 4 + p;
            int kk = kc * 32 + jp * 2;
            float v0 = We[(size_t)kk * (TT * HH) + jb * 64 + n];
            float v1 = We[(size_t)(kk + 1) * (TT * HH) + jb * 64 + n];
            int g = jp >> 3, jj = jp & 7;
            dst[n * 16 + g * 8 + 2 * (jj & 3) + (jj >> 2)] = pk2h(v0, v1);
        }
    } else if (b < 1536) {                 /* GRU weights */
        int b2 = b - 768;
        int kc = b2 & 15, jb = (b2 >> 4) & 7, mat = b2 >> 7;
        const float* Ws[6] = {W0, W1, W2, W3, W4, W5};
        const float* W = Ws[mat];
        int n = tid & 63, kg = tid >> 6;
        unsigned* dst = &g_wswg[(size_t)((mat * 8 + jb) * 16 + kc) * B_GU32];
#pragma unroll
        for (int p = 0; p < 4; p++) {
            int jp = kg * 4 + p;
            int kk = kc * 32 + jp * 2;
            float v0 = W[(size_t)kk * HH + jb * 64 + n];
            float v1 = W[(size_t)(kk + 1) * HH + jb * 64 + n];
            int g = jp >> 3, jj = jp & 7;
            dst[n * 16 + g * 8 + 2 * (jj & 3) + (jj >> 2)] = pk2h(v0, v1);
        }
    } else if (b < 1536 + CVT_BLKS) {      /* emb convert */
        size_t i = (size_t)(b - 1536) * 256 + tid;
        if (i >= (size_t)NN * 32) return;
        const float4* s4 = (const float4*)(emb + i * 16);
        float4 f0 = s4[0], f1 = s4[1], f2 = s4[2], f3 = s4[3];
        unsigned o[8];
        o[0] = pk2h(f0.x, f0.y); o[2] = pk2h(f0.z, f0.w);
        o[4] = pk2h(f1.x, f1.y); o[6] = pk2h(f1.z, f1.w);
        o[1] = pk2h(f2.x, f2.y); o[3] = pk2h(f2.z, f2.w);
        o[5] = pk2h(f3.x, f3.y); o[7] = pk2h(f3.z, f3.w);
        uint4* d4 = (uint4*)(e16 + i * 8);
        d4[0] = make_uint4(o[0], o[1], o[2], o[3]);
        d4[1] = make_uint4(o[4], o[5], o[6], o[7]);
    } else {                               /* zero g_prop16 */
        size_t i = (size_t)(b - 1536 - CVT_BLKS) * 256 + tid;
        if (i < (size_t)NN * 64)
            ((uint4*)g_prop16)[i] = make_uint4(0u, 0u, 0u, 0u);
    }
}

/* ---------------- fused GRU mma kernel (persistent) -------------------------
 * 512 threads, 16 warps, warp tile 32x16, tile 128x64, 3-stage pipe.
 * 160 resident CTAs pull tile tickets (jb fastest) from g_gtick.            */
__device__ __forceinline__ void gru_fill(uint32_t st, int m0, int jb, int kc, int tid)
{
#pragma unroll
    for (int i = 0; i < 2; i++) {             /* A: 1024 CPA16 */
        int idx = i * 512 + tid;
        int mat = idx >> 9, rq = idx & 511, r = rq >> 2, q = rq & 3;
        int rg = m0 + r; if (rg > NN - 1) rg = NN - 1;
        const unsigned* s = (mat ? g_emb16 : g_prop16) + (size_t)rg * 256 + kc * 16 + q * 4;
        CPA16(st + (mat * A_U32H + r * RSTR + q * 4) * 4, (const void*)s);
    }
#pragma unroll
    for (int i = 0; i < 3; i++) {             /* B: 1536 CPA16 */
        int gidx = i * 512 + tid;
        int m_ = gidx >> 8, idx = gidx & 255, row = idx >> 2, c = idx & 3;
        const char* src = (const char*)&g_wswg[(size_t)((m_ * 8 + jb) * 16 + kc) * B_GU32];
        CPA16(st + (GRU_BOFFH + m_ * B_U32H + row * RSTR + c * 4) * 4, src + idx * 16);
    }
    CPA_COMMIT();
}

__global__ __launch_bounds__(512, 1) void k_gru_mma(
    const float* __restrict__ emb,
    const float* __restrict__ bir, const float* __restrict__ biz,
    const float* __restrict__ bin, const float* __restrict__ bhn,
    float* __restrict__ out)
{
    extern __shared__ unsigned smu[];
    float* bias_s = (float*)smu;                 /* 256 floats */
    int*   s_tick = (int*)(smu + 256);
    unsigned* stage0 = smu + GRU_HDR_U32;
    uint32_t st0 = smem_u32(stage0);

    int tid = threadIdx.x, lane = tid & 31, warp = tid >> 5;
    int gid = lane >> 2, tig = lane & 3;
    int wm = (warp >> 2) * 32, wn = (warp & 3) * 16;

    for (;;) {
        if (tid == 0) *s_tick = atomicAdd(&g_gtick, 1);
        __syncthreads();
        int t = *s_tick;
        if (t >= NTILE) return;
        int jb = t & 7, m0 = (t >> 3) * 128;

        if (tid < 256) {
            const float* ba[4] = {bir, biz, bin, bhn};
            bias_s[tid] = ba[tid >> 6][jb * 64 + (tid & 63)];
        }

        float accR[2][2][4], accZ[2][2][4], accN[2][2][4], accH[2][2][4];
#pragma unroll
        for (int mf = 0; mf < 2; mf++)
#pragma unroll
            for (int ni = 0; ni < 2; ni++)
#pragma unroll
                for (int q = 0; q < 4; q++) {
                    accR[mf][ni][q] = 0.f; accZ[mf][ni][q] = 0.f;
                    accN[mf][ni][q] = 0.f; accH[mf][ni][q] = 0.f;
                }

        gru_fill(st0, m0, jb, 0, tid);
        gru_fill(st0 + GRU_STAGE_U32 * 4, m0, jb, 1, tid);

        for (int c = 0; c < 16; c++) {
            if (c < 15) CPA_WAIT1(); else CPA_WAIT0();
            __syncthreads();
            if (c + 2 < 16)
                gru_fill(st0 + ((c + 2) % 3) * GRU_STAGE_U32 * 4, m0, jb, c + 2, tid);

            const unsigned* cur = stage0 + (c % 3) * GRU_STAGE_U32;
            const unsigned* Ap = cur;
            const unsigned* Ah = cur + A_U32H;
            const unsigned* Bb = cur + GRU_BOFFH;
#pragma unroll
            for (int ks = 0; ks < 2; ks++) {
                int ko = ks * 8 + tig * 2;
                unsigned ap[2][4], ah[2][4];
#pragma unroll
                for (int mf = 0; mf < 2; mf++) {
                    int r0 = wm + mf * 16 + gid;
                    uint2 v0 = *(const uint2*)(Ap + r0 * RSTR + ko);
                    uint2 v1 = *(const uint2*)(Ap + (r0 + 8) * RSTR + ko);
                    ap[mf][0] = v0.x; ap[mf][1] = v1.x; ap[mf][2] = v0.y; ap[mf][3] = v1.y;
                    uint2 w0 = *(const uint2*)(Ah + r0 * RSTR + ko);
                    uint2 w1 = *(const uint2*)(Ah + (r0 + 8) * RSTR + ko);
                    ah[mf][0] = w0.x; ah[mf][1] = w1.x; ah[mf][2] = w0.y; ah[mf][3] = w1.y;
                }
#pragma unroll
                for (int ni = 0; ni < 2; ni++) {
                    int cb = (wn + ni * 8 + gid) * RSTR + ko;
                    uint2 b;
                    b = *(const uint2*)(Bb + 0 * B_U32H + cb);   /* Wir */
#pragma unroll
                    for (int mf = 0; mf < 2; mf++) mma16(accR[mf][ni], ap[mf], b);
                    b = *(const uint2*)(Bb + 1 * B_U32H + cb);   /* Whr */
#pragma unroll
                    for (int mf = 0; mf < 2; mf++) mma16(accR[mf][ni], ah[mf], b);
                    b = *(const uint2*)(Bb + 2 * B_U32H + cb);   /* Wiz */
#pragma unroll
                    for (int mf = 0; mf < 2; mf++) mma16(accZ[mf][ni], ap[mf], b);
                    b = *(const uint2*)(Bb + 3 * B_U32H + cb);   /* Whz */
#pragma unroll
                    for (int mf = 0; mf < 2; mf++) mma16(accZ[mf][ni], ah[mf], b);
                    b = *(const uint2*)(Bb + 4 * B_U32H + cb);   /* Win */
#pragma unroll
                    for (int mf = 0; mf < 2; mf++) mma16(accN[mf][ni], ap[mf], b);
                    b = *(const uint2*)(Bb + 5 * B_U32H + cb);   /* Whn */
#pragma unroll
                    for (int mf = 0; mf < 2; mf++) mma16(accH[mf][ni], ah[mf], b);
                }
            }
        }

        /* epilogue: gates (h read in fp32) */
#pragma unroll
        for (int mf = 0; mf < 2; mf++) {
#pragma unroll
            for (int rp = 0; rp < 2; rp++) {
                int row = m0 + wm + mf * 16 + rp * 8 + gid;
                if (row >= NN) continue;
                const float* hrow = emb + (size_t)row * HH + jb * 64;
                float* orow = out + (size_t)row * HH + jb * 64;
#pragma unroll
                for (int ni = 0; ni < 2; ni++) {
                    int c0 = wn + ni * 8 + tig * 2;
                    float2 h2 = *(const float2*)(hrow + c0);
                    float o[2];
#pragma unroll
                    for (int e = 0; e < 2; e++) {
                        int q = rp * 2 + e;
                        int cl = c0 + e;
                        float r = sigmoidf_(accR[mf][ni][q] + bias_s[cl]);
                        float z = sigmoidf_(accZ[mf][ni][q] + bias_s[64 + cl]);
                        float n = tanhf(accN[mf][ni][q] + bias_s[128 + cl]
                                        + r * (accH[mf][ni][q] + bias_s[192 + cl]));
                        float h = e ? h2.y : h2.x;
                        o[e] = (1.f - z) * n + z * h;
                    }
                    *(float2*)(orow + c0) = make_float2(o[0], o[1]);
                }
            }
        }
        __syncthreads();     /* protect bias_s / stages before next tile */
    }
}

/* ---------------- edge mma kernel ------------------------------------------
 * 256 threads, 8 warps, warp tile 64x32, CTA tile 256x64. 3-stage pipe,
 * 2 CTAs/SM. fp16x2 REDs directly into interleaved g_prop16.                */
__device__ __forceinline__ void edge_fill(uint32_t st, const int* __restrict__ ssrc,
                                          int jbg, int kc, int tid)
{
#pragma unroll
    for (int i = 0; i < 4; i++) {             /* A: 1024 CPA16 */
        int idx = i * 256 + tid, r = idx >> 2, q = idx & 3;
        int nr = ssrc[r]; if (nr < 0) nr = 0;
        const unsigned* s = g_emb16 + (size_t)nr * 256 + kc * 16 + q * 4;
        CPA16(st + (r * RSTR + q * 4) * 4, (const void*)s);
    }
    {                                          /* B: 256 CPA16 */
        int row = tid >> 2, c = tid & 3;
        const char* src = (const char*)&g_wswe[(size_t)(jbg * 16 + kc) * B_GU32];
        CPA16(st + (EDGE_A_U32 + row * RSTR + c * 4) * 4, src + tid * 16);
    }
    CPA_COMMIT();
}

__global__ __launch_bounds__(256, 2) void k_edge_mma(
    const int* __restrict__ src, const int* __restrict__ dst,
    const float* __restrict__ b_edge)
{
    int start = blockIdx.y * 256;
    if (start >= g_toff[TT]) return;
    int t = 0;
#pragma unroll
    for (int i = 1; i < TT; i++) if (start >= g_toff[i]) t = i;
    int jb8 = blockIdx.x;
    int jbg = t * 8 + jb8;

    extern __shared__ unsigned smu[];
    int* s_srow = (int*)smu;             /* 256 */
    int* s_dst  = (int*)smu + 256;       /* 256 */
    float* s_bias = (float*)smu + 512;   /* 64  */
    unsigned* stage0 = smu + EDGE_HDR_U32;
    uint32_t st0 = smem_u32(stage0);

    int tid = threadIdx.x, lane = tid & 31, warp = tid >> 5;
    int gid = lane >> 2, tig = lane & 3;
    int wm = (warp >> 1) * 64, wn = (warp & 1) * 32;

    {
        int e = g_sorted[start + tid];
        s_srow[tid] = (e >= 0) ? src[e] : -1;
        s_dst[tid]  = (e >= 0) ? dst[e] : -1;
    }
    if (tid < 64) s_bias[tid] = b_edge[(size_t)t * HH + jb8 * 64 + tid];
    __syncthreads();

    float acc[4][4][4];
#pragma unroll
    for (int mf = 0; mf < 4; mf++)
#pragma unroll
        for (int ni = 0; ni < 4; ni++)
#pragma unroll
            for (int q = 0; q < 4; q++) acc[mf][ni][q] = 0.f;

    edge_fill(st0, s_srow, jbg, 0, tid);
    edge_fill(st0 + EDGE_STAGE_U32 * 4, s_srow, jbg, 1, tid);

    for (int c = 0; c < 16; c++) {
        if (c < 15) CPA_WAIT1(); else CPA_WAIT0();
        __syncthreads();
        if (c + 2 < 16)
            edge_fill(st0 + ((c + 2) % 3) * EDGE_STAGE_U32 * 4, s_srow, jbg, c + 2, tid);

        const unsigned* cur = stage0 + (c % 3) * EDGE_STAGE_U32;
        const unsigned* Ap = cur;
        const unsigned* Bb = cur + EDGE_A_U32;
#pragma unroll
        for (int ks = 0; ks < 2; ks++) {
            int ko = ks * 8 + tig * 2;
            unsigned ap[4][4];
#pragma unroll
            for (int mf = 0; mf < 4; mf++) {
                int r0 = wm + mf * 16 + gid;
                uint2 v0 = *(const uint2*)(Ap + r0 * RSTR + ko);
                uint2 v1 = *(const uint2*)(Ap + (r0 + 8) * RSTR + ko);
                ap[mf][0] = v0.x; ap[mf][1] = v1.x; ap[mf][2] = v0.y; ap[mf][3] = v1.y;
            }
#pragma unroll
            for (int ni = 0; ni < 4; ni++) {
                uint2 b = *(const uint2*)(Bb + (wn + ni * 8 + gid) * RSTR + ko);
#pragma unroll
                for (int mf = 0; mf < 4; mf++) mma16(acc[mf][ni], ap[mf], b);
            }
        }
    }

    /* epilogue: bias + fp16x2 scatter reduction into interleaved g_prop16 */
#pragma unroll
    for (int mf = 0; mf < 4; mf++) {
#pragma unroll
        for (int rp = 0; rp < 2; rp++) {
            int arow = wm + mf * 16 + rp * 8 + gid;
            int d = s_dst[arow];
            if (d < 0) continue;
            unsigned* prow = g_prop16 + (size_t)d * 256;
#pragma unroll
            for (int ni = 0; ni < 4; ni++) {
                int cl = wn + ni * 8 + tig * 2;          /* local col (even) */
                int c0 = jb8 * 64 + cl;                  /* global col       */
                int pg = (c0 >> 1) & 7;                  /* pair in 16-group */
                int u32idx = (c0 >> 4) * 8 + 2 * (pg & 3) + (pg >> 2);
                unsigned v = pk2h(acc[mf][ni][rp * 2]     + s_bias[cl],
                                  acc[mf][ni][rp * 2 + 1] + s_bias[cl + 1]);
                redh2(prow + u32idx, v);
            }
        }
    }
}

/* ---------------- launch --------------------------------------------------- */
extern "C" void kernel_launch(void* const* d_in, const int* in_sizes, int n_in,
                              void* d_out, int out_size)
{
    int s = (n_in >= 18) ? 2 : 0;

    const float* emb    = (const float*)d_in[0];
    const int*   src    = (const int*)d_in[1];
    const int*   dst    = (const int*)d_in[2];
    const int*   et     = (const int*)d_in[3];
    const float* W_edge = (const float*)d_in[4 + s];
    const float* b_edge = (const float*)d_in[5 + s];
    const float* Wir    = (const float*)d_in[6 + s];
    const float* Wiz    = (const float*)d_in[7 + s];
    const float* Win    = (const float*)d_in[8 + s];
    const float* bir    = (const float*)d_in[9 + s];
    const float* biz    = (const float*)d_in[10 + s];
    const float* bin    = (const float*)d_in[11 + s];
    const float* Whr    = (const float*)d_in[12 + s];
    const float* Whz    = (const float*)d_in[13 + s];
    const float* Whn    = (const float*)d_in[14 + s];
    const float* bhn    = (const float*)d_in[15 + s];
    float* out = (float*)d_out;

    unsigned* d_e16;  cudaGetSymbolAddress((void**)&d_e16, g_emb16);

    static int init_done = 0;
    static cudaStream_t s2 = 0;
    static cudaEvent_t ev1 = 0, ev2 = 0;
    if (!init_done) {
        cudaFuncSetAttribute(k_gru_mma,  cudaFuncAttributeMaxDynamicSharedMemorySize, GRU_SMEMH);
        cudaFuncSetAttribute(k_edge_mma, cudaFuncAttributeMaxDynamicSharedMemorySize, EDGE_SMEMH);
        if (cudaStreamCreateWithFlags(&s2, cudaStreamNonBlocking) != cudaSuccess) s2 = 0;
        if (s2) {
            if (cudaEventCreateWithFlags(&ev1, cudaEventDisableTiming) != cudaSuccess) { ev1 = 0; }
            if (cudaEventCreateWithFlags(&ev2, cudaEventDisableTiming) != cudaSuccess) { ev2 = 0; }
            if (!ev1 || !ev2) s2 = 0;
        }
        init_done = 1;
    }

    if (s2) {
        /* fork: prep on s2 concurrent with sort chain on default stream */
        cudaEventRecord(ev1, 0);
        cudaStreamWaitEvent(s2, ev1, 0);
        k_prep_all<<<1536 + CVT_BLKS + ZERO_BLKS, 256, 0, s2>>>(
            W_edge, Wir, Whr, Wiz, Whz, Win, Whn, emb, d_e16);
        cudaEventRecord(ev2, s2);

        k_init<<<(SORT_CAP + 255) / 256, 256>>>();
        k_hist<<<(EE + 255) / 256, 256>>>(et);
        k_scatter<<<(EE + 255) / 256, 256>>>(et);

        cudaStreamWaitEvent((cudaStream_t)0, ev2, 0);
    } else {
        k_init<<<(SORT_CAP + 255) / 256, 256>>>();
        k_hist<<<(EE + 255) / 256, 256>>>(et);
        k_scatter<<<(EE + 255) / 256, 256>>>(et);
        k_prep_all<<<1536 + CVT_BLKS + ZERO_BLKS, 256>>>(
            W_edge, Wir, Whr, Wiz, Whz, Win, Whn, emb, d_e16);
    }

    k_edge_mma<<<dim3(8, EGRP), 256, EDGE_SMEMH>>>(src, dst, b_edge);

    k_gru_mma<<<160, 512, GRU_SMEMH>>>(emb, bir, biz, bin, bhn, out);
}